// round 4
// baseline (speedup 1.0000x reference)
#include <cuda_runtime.h>
#include <cstdint>

#define BATCH 16
#define NCLS 7
#define HH 368
#define WW 640
#define NSEG (BATCH * 6)

// Packed per-(b, class, row) stats: bits[0:10)=min col, [10:20)=max col,
// [20:31)=count (0 means empty row for this class).
__device__ unsigned g_row[NSEG * HH];
__device__ float g_bpart[BATCH];
__device__ int g_rowdone[BATCH];
__device__ int g_bdone = 0;

// -------------------------------------------------------------------------
// Single fused kernel. Phase A (all 5888 blocks): per-pixel class via
// soft-argmax -> per-row per-class (min col, max col, count), packed store.
// Phase B (last block per batch): combine 368 rows x 6 classes for that
// batch. Phase C (last batch finisher): deterministic fixed-order sum of 16
// batch partials -> out[0]. Counters self-reset for graph replay.
// -------------------------------------------------------------------------
__device__ __forceinline__ int pix_class(const float l[7]) {
    float e0 = __expf(l[0]);
    float e1 = __expf(l[1]);
    float e2 = __expf(l[2]);
    float e3 = __expf(l[3]);
    float e4 = __expf(l[4]);
    float e5 = __expf(l[5]);
    float e6 = __expf(l[6]);
    float den = ((e0 + e1) + (e2 + e3)) + ((e4 + e5) + e6);
    float num = e1;
    num = fmaf(2.0f, e2, num);
    num = fmaf(3.0f, e3, num);
    num = fmaf(4.0f, e4, num);
    num = fmaf(5.0f, e5, num);
    num = fmaf(6.0f, e6, num);
    // num/den in [0,6]; truncation == floor for non-negative values.
    float r = __fdividef(num, den);
    return (int)r;
}

__global__ __launch_bounds__(160) void k_fused(float* __restrict__ out,
                                               const float* __restrict__ logits) {
    const int row  = blockIdx.x;
    const int b    = blockIdx.y;
    const int t    = threadIdx.x;
    const int lane = t & 31;
    const int warp = t >> 5;
    const int col0 = t << 2;   // 4 pixels per thread

    // ---------------- Phase A: row stats ----------------
    float4 v[NCLS];
#pragma unroll
    for (int c = 0; c < NCLS; c++) {
        const float* p = logits + (((size_t)b * NCLS + c) * HH + row) * WW + col0;
        v[c] = *reinterpret_cast<const float4*>(p);
    }

    int k0, k1, k2, k3;
    {
        float l[7];
#pragma unroll
        for (int c = 0; c < NCLS; c++) l[c] = v[c].x;
        k0 = pix_class(l);
#pragma unroll
        for (int c = 0; c < NCLS; c++) l[c] = v[c].y;
        k1 = pix_class(l);
#pragma unroll
        for (int c = 0; c < NCLS; c++) l[c] = v[c].z;
        k2 = pix_class(l);
#pragma unroll
        for (int c = 0; c < NCLS; c++) l[c] = v[c].w;
        k3 = pix_class(l);
    }

    // One-hot bitboard: byte j holds (1 << class_of_pixel_j).
    const unsigned B = (1u << k0) | (1u << (k1 + 8)) | (1u << (k2 + 16)) | (1u << (k3 + 24));

    __shared__ int smn[5][6], smx[5][6], sct[5][6];

#pragma unroll
    for (int c = 1; c <= 6; c++) {
        unsigned m = (B >> c) & 0x01010101u;  // bit 8*j set iff pixel j is class c
        int cnt = __popc(m);
        int mnl = m ? col0 + ((__ffs(m) - 1) >> 3) : 0x7fffffff;
        int mxl = m ? col0 + ((31 - __clz(m)) >> 3) : -1;
        int wmn = __reduce_min_sync(0xffffffffu, mnl);
        int wmx = __reduce_max_sync(0xffffffffu, mxl);
        int wct = __reduce_add_sync(0xffffffffu, cnt);
        if (lane == 0) {
            smn[warp][c - 1] = wmn;
            smx[warp][c - 1] = wmx;
            sct[warp][c - 1] = wct;
        }
    }
    __syncthreads();

    if (t < 6) {
        int fmn = 0x7fffffff, fmx = -1, fct = 0;
#pragma unroll
        for (int w = 0; w < 5; w++) {
            fmn = min(fmn, smn[w][t]);
            fmx = max(fmx, smx[w][t]);
            fct += sct[w][t];
        }
        const int idx = ((b * 6 + t) * HH) + row;
        unsigned pk = (fct == 0) ? 0u
            : ((unsigned)fmn | ((unsigned)fmx << 10) | ((unsigned)fct << 20));
        g_row[idx] = pk;
    }

    // ---------------- Phase B gate: last block of this batch ----------------
    __shared__ int s_last;
    __threadfence();
    if (t == 0) {
        int old = atomicAdd(&g_rowdone[b], 1);
        s_last = (old == HH - 1);
    }
    __syncthreads();
    if (!s_last) return;

    // This block is batch b's finisher. 5 warps cover 6 segments.
    __shared__ float s_loss[6];

    for (int cls = warp; cls < 6; cls += 5) {
        const int base = (b * 6 + cls) * HH;

        int valid = 0, cnt = 0, S = 0;
        int fcol = 0, frow = 0, lcol = 0, lrow = 0;

        const int r0 = lane * 12;
        const int r1 = min(HH, r0 + 12);
        for (int r = r0; r < r1; r++) {
            unsigned pk = __ldcg(&g_row[base + r]);
            int c = pk >> 20;
            if (!c) continue;
            int mnv = pk & 1023;
            int mxv = (pk >> 10) & 1023;
            if (valid) {
                S += abs((mnv - r) - (lcol - lrow));
            } else {
                fcol = mnv; frow = r; valid = 1;
            }
            S += mxv - mnv;
            lcol = mxv; lrow = r; cnt += c;
        }

        // Ordered tree reduction: lane absorbs segment from lane+off.
#pragma unroll
        for (int off = 1; off < 32; off <<= 1) {
            int ov  = __shfl_down_sync(0xffffffffu, valid, off);
            int oc  = __shfl_down_sync(0xffffffffu, cnt, off);
            int oS  = __shfl_down_sync(0xffffffffu, S, off);
            int ofc = __shfl_down_sync(0xffffffffu, fcol, off);
            int ofr = __shfl_down_sync(0xffffffffu, frow, off);
            int olc = __shfl_down_sync(0xffffffffu, lcol, off);
            int olr = __shfl_down_sync(0xffffffffu, lrow, off);
            if ((lane & (2 * off - 1)) == 0 && ov) {
                if (valid) {
                    S += oS + abs((ofc - ofr) - (lcol - lrow));
                } else {
                    S = oS; fcol = ofc; frow = ofr; valid = 1;
                }
                cnt += oc;
                lcol = olc; lrow = olr;
            }
        }

        if (lane == 0) {
            float loss = 0.0f;
            if (cnt >= 2) {
                loss = ((float)S / (float)(cnt - 1)) / (float)(cnt + 1);
            }
            s_loss[cls] = loss;
        }
    }
    __syncthreads();

    // ---------------- Phase C: batch partial + global finish ----------------
    if (t == 0) {
        float bsum = ((s_loss[0] + s_loss[1]) + (s_loss[2] + s_loss[3]))
                   + (s_loss[4] + s_loss[5]);
        g_bpart[b] = bsum;
        g_rowdone[b] = 0;  // reset for next graph replay (we were the last user)
        __threadfence();
        int old = atomicAdd(&g_bdone, 1);
        if (old == BATCH - 1) {
            float s = 0.0f;
#pragma unroll
            for (int i = 0; i < BATCH; i++) s += g_bpart[i];  // fixed order
            out[0] = s;
            g_bdone = 0;  // reset for next graph replay
        }
    }
}

extern "C" void kernel_launch(void* const* d_in, const int* in_sizes, int n_in,
                              void* d_out, int out_size) {
    const float* logits = (const float*)d_in[0];
    // d_in[1] (labels) is unused by the reference computation.
    dim3 g1(HH, BATCH);
    k_fused<<<g1, 160>>>((float*)d_out, logits);
}

// round 5
// speedup vs baseline: 1.0012x; 1.0012x over previous
#include <cuda_runtime.h>
#include <cstdint>

#define BATCH 16
#define NCLS 7
#define HH 368
#define WW 640
#define NSEG (BATCH * 6)

// Packed per-(b, class, row) stats: bits[0:10)=min col, [10:20)=max col,
// [20:31)=count (0 means empty row for this class).
__device__ unsigned g_row[NSEG * HH];
__device__ float g_part[NSEG];
__device__ int g_done = 0;

// -------------------------------------------------------------------------
// Kernel 1: per-pixel class via soft-argmax -> per-row per-class
// (min col, max col, count). One block per (row, batch); 160 threads,
// 4 consecutive pixels each (streaming float4 per class plane).
// -------------------------------------------------------------------------
__device__ __forceinline__ int pix_class(const float l[7]) {
    float e0 = __expf(l[0]);
    float e1 = __expf(l[1]);
    float e2 = __expf(l[2]);
    float e3 = __expf(l[3]);
    float e4 = __expf(l[4]);
    float e5 = __expf(l[5]);
    float e6 = __expf(l[6]);
    float den = ((e0 + e1) + (e2 + e3)) + ((e4 + e5) + e6);
    float num = e1;
    num = fmaf(2.0f, e2, num);
    num = fmaf(3.0f, e3, num);
    num = fmaf(4.0f, e4, num);
    num = fmaf(5.0f, e5, num);
    num = fmaf(6.0f, e6, num);
    // num/den in [0,6]; truncation == floor for non-negative values.
    float r = __fdividef(num, den);
    return (int)r;
}

__global__ __launch_bounds__(160) void k_rowstats(const float* __restrict__ logits) {
    const int row  = blockIdx.x;
    const int b    = blockIdx.y;
    const int t    = threadIdx.x;
    const int lane = t & 31;
    const int warp = t >> 5;
    const int col0 = t << 2;   // 4 pixels per thread

    float4 v[NCLS];
#pragma unroll
    for (int c = 0; c < NCLS; c++) {
        const float* p = logits + (((size_t)b * NCLS + c) * HH + row) * WW + col0;
        v[c] = __ldcs(reinterpret_cast<const float4*>(p));  // streaming: no reuse
    }

    int k0, k1, k2, k3;
    {
        float l[7];
#pragma unroll
        for (int c = 0; c < NCLS; c++) l[c] = v[c].x;
        k0 = pix_class(l);
#pragma unroll
        for (int c = 0; c < NCLS; c++) l[c] = v[c].y;
        k1 = pix_class(l);
#pragma unroll
        for (int c = 0; c < NCLS; c++) l[c] = v[c].z;
        k2 = pix_class(l);
#pragma unroll
        for (int c = 0; c < NCLS; c++) l[c] = v[c].w;
        k3 = pix_class(l);
    }

    // One-hot bitboard: byte j holds (1 << class_of_pixel_j).
    const unsigned B = (1u << k0) | (1u << (k1 + 8)) | (1u << (k2 + 16)) | (1u << (k3 + 24));

    __shared__ int smn[5][6], smx[5][6], sct[5][6];

#pragma unroll
    for (int c = 1; c <= 6; c++) {
        unsigned m = (B >> c) & 0x01010101u;  // bit 8*j set iff pixel j is class c
        int cnt = __popc(m);
        int mnl = m ? col0 + ((__ffs(m) - 1) >> 3) : 0x7fffffff;
        int mxl = m ? col0 + ((31 - __clz(m)) >> 3) : -1;
        int wmn = __reduce_min_sync(0xffffffffu, mnl);
        int wmx = __reduce_max_sync(0xffffffffu, mxl);
        int wct = __reduce_add_sync(0xffffffffu, cnt);
        if (lane == 0) {
            smn[warp][c - 1] = wmn;
            smx[warp][c - 1] = wmx;
            sct[warp][c - 1] = wct;
        }
    }
    __syncthreads();

    if (t < 6) {
        int fmn = 0x7fffffff, fmx = -1, fct = 0;
#pragma unroll
        for (int w = 0; w < 5; w++) {
            fmn = min(fmn, smn[w][t]);
            fmx = max(fmx, smx[w][t]);
            fct += sct[w][t];
        }
        const int idx = ((b * 6 + t) * HH) + row;
        unsigned pk = (fct == 0) ? 0u
            : ((unsigned)fmn | ((unsigned)fmx << 10) | ((unsigned)fct << 20));
        g_row[idx] = pk;
    }
}

// -------------------------------------------------------------------------
// Kernel 2: one block per segment (96 blocks, 384 threads), launched with
// PDL so its prologue overlaps k_rowstats; cudaGridDependencySynchronize()
// gates the g_row reads. Thread r loads row r's packed stats; ordered
// merges (5 warp shuffle steps + one cross-warp merge). The last block sums
// the 96 partials in fixed order and writes the scalar.
// -------------------------------------------------------------------------
__global__ __launch_bounds__(384) void k_combine(float* __restrict__ out) {
    const int seg  = blockIdx.x;
    const int t    = threadIdx.x;
    const int lane = t & 31;
    const int w    = t >> 5;

    // Overlap-friendly prologue done; now wait for producer grid.
    cudaGridDependencySynchronize();

    int valid = 0, cnt = 0, S = 0;
    int fcol = 0, frow = 0, lcol = 0, lrow = 0;

    if (t < HH) {
        unsigned pk = g_row[seg * HH + t];
        cnt = pk >> 20;
        if (cnt) {
            int mnv = pk & 1023;
            int mxv = (pk >> 10) & 1023;
            valid = 1;
            S = mxv - mnv;
            fcol = mnv; frow = t;
            lcol = mxv; lrow = t;
        }
    }

    // Ordered warp tree: lane absorbs the segment from lane+off (its right).
#pragma unroll
    for (int off = 1; off < 32; off <<= 1) {
        int ov  = __shfl_down_sync(0xffffffffu, valid, off);
        int oc  = __shfl_down_sync(0xffffffffu, cnt, off);
        int oS  = __shfl_down_sync(0xffffffffu, S, off);
        int ofc = __shfl_down_sync(0xffffffffu, fcol, off);
        int ofr = __shfl_down_sync(0xffffffffu, frow, off);
        int olc = __shfl_down_sync(0xffffffffu, lcol, off);
        int olr = __shfl_down_sync(0xffffffffu, lrow, off);
        if ((lane & (2 * off - 1)) == 0 && ov) {
            if (valid) {
                S += oS + abs((ofc - ofr) - (lcol - lrow));
            } else {
                S = oS; fcol = ofc; frow = ofr; valid = 1;
            }
            cnt += oc;
            lcol = olc; lrow = olr;
        }
    }

    __shared__ int sv[16], sc[16], sS[16], sfc[16], sfr[16], slc[16], slr[16];
    if (t < 16) sv[t] = 0;  // pad warps 12..15 as invalid
    __syncthreads();
    if (lane == 0) {
        sv[w] = valid; sc[w] = cnt; sS[w] = S;
        sfc[w] = fcol; sfr[w] = frow; slc[w] = lcol; slr[w] = lrow;
    }
    __syncthreads();

    if (w == 0) {
        if (lane < 16) {
            valid = sv[lane]; cnt = sc[lane]; S = sS[lane];
            fcol = sfc[lane]; frow = sfr[lane]; lcol = slc[lane]; lrow = slr[lane];
        } else {
            valid = 0; cnt = 0; S = 0; fcol = frow = lcol = lrow = 0;
        }
#pragma unroll
        for (int off = 1; off < 16; off <<= 1) {
            int ov  = __shfl_down_sync(0xffffffffu, valid, off);
            int oc  = __shfl_down_sync(0xffffffffu, cnt, off);
            int oS  = __shfl_down_sync(0xffffffffu, S, off);
            int ofc = __shfl_down_sync(0xffffffffu, fcol, off);
            int ofr = __shfl_down_sync(0xffffffffu, frow, off);
            int olc = __shfl_down_sync(0xffffffffu, lcol, off);
            int olr = __shfl_down_sync(0xffffffffu, lrow, off);
            if ((lane & (2 * off - 1)) == 0 && ov) {
                if (valid) {
                    S += oS + abs((ofc - ofr) - (lcol - lrow));
                } else {
                    S = oS; fcol = ofc; frow = ofr; valid = 1;
                }
                cnt += oc;
                lcol = olc; lrow = olr;
            }
        }
        if (lane == 0) {
            float loss = 0.0f;
            if (cnt >= 2) {
                loss = ((float)S / (float)(cnt - 1)) / (float)(cnt + 1);
            }
            g_part[seg] = loss;
        }
    }

    // Last block finalizes: deterministic (integer counter, fixed sum order).
    __shared__ int s_last;
    __threadfence();
    if (t == 0) {
        int old = atomicAdd(&g_done, 1);
        s_last = (old == NSEG - 1);
    }
    __syncthreads();

    if (s_last && w == 0) {
        float v = g_part[lane] + g_part[lane + 32] + g_part[lane + 64];
#pragma unroll
        for (int off = 16; off > 0; off >>= 1)
            v += __shfl_down_sync(0xffffffffu, v, off);
        if (lane == 0) {
            out[0] = v;
            g_done = 0;  // reset for next graph replay
        }
    }
}

extern "C" void kernel_launch(void* const* d_in, const int* in_sizes, int n_in,
                              void* d_out, int out_size) {
    const float* logits = (const float*)d_in[0];
    // d_in[1] (labels) is unused by the reference computation.
    dim3 g1(HH, BATCH);
    k_rowstats<<<g1, 160>>>(logits);

    // PDL: k_combine launches while k_rowstats drains; its
    // cudaGridDependencySynchronize() gates consumption of g_row.
    cudaLaunchConfig_t cfg = {};
    cfg.gridDim = dim3(NSEG);
    cfg.blockDim = dim3(384);
    cudaLaunchAttribute attrs[1];
    attrs[0].id = cudaLaunchAttributeProgrammaticStreamSerialization;
    attrs[0].val.programmaticStreamSerializationAllowed = 1;
    cfg.attrs = attrs;
    cfg.numAttrs = 1;
    float* out = (float*)d_out;
    cudaLaunchKernelEx(&cfg, k_combine, out);
}